// round 9
// baseline (speedup 1.0000x reference)
#include <cuda_runtime.h>
#include <cuda_fp16.h>
#include <math.h>

#define EMBED 1024
#define HEAD  128
#define BATCH 8
#define SEQ   2048
#define MTOT  (BATCH*SEQ)

// Scratch (allocation-free). All values stored as fp16.
__device__ __half g_q[MTOT * HEAD];          // pre-scaled by log2(e)/32
__device__ __half g_k[MTOT * HEAD];
__device__ __half g_vt[MTOT * HEAD];         // V transposed: [b][h][s]
__device__ __half g_wt[3][HEAD][EMBED];      // W^T fp16: [z][n][k]

// ---------------------------------------------------------------------------
// helpers
// ---------------------------------------------------------------------------
__device__ __forceinline__ unsigned packh2(float a, float b) {
    __half2 h = __floats2half2_rn(a, b);
    return *reinterpret_cast<unsigned*>(&h);
}
__device__ __forceinline__ void mma_f16(float d[4],
                                        unsigned a0, unsigned a1, unsigned a2, unsigned a3,
                                        unsigned b0, unsigned b1) {
    asm volatile(
        "mma.sync.aligned.m16n8k16.row.col.f32.f16.f16.f32 "
        "{%0,%1,%2,%3}, {%4,%5,%6,%7}, {%8,%9}, {%0,%1,%2,%3};"
        : "+f"(d[0]), "+f"(d[1]), "+f"(d[2]), "+f"(d[3])
        : "r"(a0), "r"(a1), "r"(a2), "r"(a3), "r"(b0), "r"(b1));
}
__device__ __forceinline__ void ldsm4(unsigned m[4], unsigned saddr) {
    asm volatile("ldmatrix.sync.aligned.m8n8.x4.shared.b16 {%0,%1,%2,%3}, [%4];"
                 : "=r"(m[0]), "=r"(m[1]), "=r"(m[2]), "=r"(m[3]) : "r"(saddr));
}
__device__ __forceinline__ void cpasync16(unsigned dst, const void* src) {
    asm volatile("cp.async.ca.shared.global [%0], [%1], 16;" :: "r"(dst), "l"(src));
}
#define CP_COMMIT asm volatile("cp.async.commit_group;")
#define CP_WAIT0  asm volatile("cp.async.wait_group 0;" ::: "memory")
#define CP_WAIT1  asm volatile("cp.async.wait_group 1;" ::: "memory")

// ---------------------------------------------------------------------------
// Prep: smem-tiled transpose + fp16 round of W into g_wt[z][n][k].
// 64 k-rows per block; coalesced float4 loads, 8B coalesced fp16 stores.
// ---------------------------------------------------------------------------
__global__ __launch_bounds__(256) void w_prep(const float* __restrict__ Wq,
                                              const float* __restrict__ Wk,
                                              const float* __restrict__ Wv)
{
    const int z = blockIdx.y;
    const float* W = (z == 0) ? Wq : (z == 1) ? Wk : Wv;
    const int k0 = blockIdx.x * 64;
    __shared__ float T[64 * 133];
    const int tid = threadIdx.x;

    // load 64 x 128 floats (coalesced)
#pragma unroll
    for (int p = 0; p < 8; p++) {
        int i = tid + p * 256;
        int row = i >> 5, c4 = i & 31;
        float4 v = *reinterpret_cast<const float4*>(&W[(size_t)(k0 + row) * HEAD + c4 * 4]);
        float* t = &T[row * 133 + c4 * 4];
        t[0] = v.x; t[1] = v.y; t[2] = v.z; t[3] = v.w;
    }
    __syncthreads();

    // write 128 n-rows x 64 k-halves (uint2 = 4 halves, coalesced per row)
#pragma unroll
    for (int p = 0; p < 8; p++) {
        int i = tid + p * 256;
        int n = i >> 4, c = i & 15;
        float a = T[(c * 4 + 0) * 133 + n];
        float b = T[(c * 4 + 1) * 133 + n];
        float cc = T[(c * 4 + 2) * 133 + n];
        float d = T[(c * 4 + 3) * 133 + n];
        uint2 u = make_uint2(packh2(a, b), packh2(cc, d));
        *reinterpret_cast<uint2*>(&g_wt[z][n][k0 + c * 4]) = u;
    }
}

// ---------------------------------------------------------------------------
// Kernel A: QKV projection (fp16 mma, m16n8k16), double-buffered.
// 256 threads, 8 warps (4m x 2n), warp tile m32 x n64, K-chunk 32 (2 k-steps).
// z==2 (V) output transposed via smem epilogue.
// ---------------------------------------------------------------------------
#define XS_H (128 * 40)
#define WS_H (128 * 40)
__global__ __launch_bounds__(256, 2) void qkv_mma(const float* __restrict__ x)
{
    __shared__ __half smh[2 * XS_H + 2 * WS_H];   // 40960 B
    __half* Xs[2] = { smh, smh + XS_H };

    const int z = blockIdx.z;
    __half* out = (z == 0) ? g_q : g_k;          // z==2 via transpose path
    // Q pre-scale: (1/sqrt(1024)) * log2(e)  -> softmax uses exp2
    const float oscale = (z == 0) ? 0.045084295033136845f : 1.0f;

    const int tid = threadIdx.x;
    const int wid = tid >> 5, lane = tid & 31;
    const int qi = lane >> 2, qj = lane & 3;
    const int g  = lane >> 3, r = lane & 7;
    const int l16 = lane & 15, hi16 = lane >> 4;
    const int wm = wid >> 1, wn = wid & 1;
    const int m0 = blockIdx.x * 128;

    const unsigned SB = (unsigned)__cvta_generic_to_shared(smh);
    const unsigned XsB[2] = { SB, SB + XS_H * 2 };
    const unsigned WtB[2] = { SB + 2 * XS_H * 2, SB + 2 * XS_H * 2 + WS_H * 2 };

    float c[2][8][4];
#pragma unroll
    for (int mt = 0; mt < 2; mt++)
#pragma unroll
        for (int nt = 0; nt < 8; nt++)
#pragma unroll
            for (int e = 0; e < 4; e++) c[mt][nt][e] = 0.f;

    const float* xbase = x + (size_t)m0 * EMBED;

    // prologue: stage chunk 0
    {
#pragma unroll
        for (int p = 0; p < 2; p++) {
            int i = tid + p * 256;
            int row = i >> 2, c4 = i & 3;
            cpasync16(WtB[0] + (unsigned)(row * 80 + c4 * 16),
                      &g_wt[z][row][c4 * 8]);
        }
        CP_COMMIT;
#pragma unroll
        for (int p = 0; p < 4; p++) {
            int i = tid + p * 256;
            int row = i >> 3, c4 = i & 7;
            float4 v = *reinterpret_cast<const float4*>(
                &xbase[(size_t)row * EMBED + c4 * 4]);
            uint2 u = make_uint2(packh2(v.x, v.y), packh2(v.z, v.w));
            *reinterpret_cast<uint2*>(&Xs[0][row * 40 + c4 * 4]) = u;
        }
    }

    for (int ch = 0; ch < 32; ch++) {
        const int cur = ch & 1, nxt = cur ^ 1;
        CP_WAIT0;
        __syncthreads();

        float4 xr[4];
        if (ch < 31) {
            const int k0n = (ch + 1) * 32;
#pragma unroll
            for (int p = 0; p < 2; p++) {
                int i = tid + p * 256;
                int row = i >> 2, c4 = i & 3;
                cpasync16(WtB[nxt] + (unsigned)(row * 80 + c4 * 16),
                          &g_wt[z][row][k0n + c4 * 8]);
            }
            CP_COMMIT;
#pragma unroll
            for (int p = 0; p < 4; p++) {
                int i = tid + p * 256;
                int row = i >> 3, c4 = i & 7;
                xr[p] = *reinterpret_cast<const float4*>(
                    &xbase[(size_t)row * EMBED + k0n + c4 * 4]);
            }
        }

        // compute: 2 k16 steps
#pragma unroll
        for (int ks = 0; ks < 2; ks++) {
            unsigned a[2][4];
#pragma unroll
            for (int mt = 0; mt < 2; mt++)
                ldsm4(a[mt], XsB[cur] + (unsigned)((wm * 32 + mt * 16 + l16) * 80
                                                   + hi16 * 16 + ks * 32));
#pragma unroll
            for (int np = 0; np < 4; np++) {
                unsigned bm[4];
                ldsm4(bm, WtB[cur] + (unsigned)(((g >> 1) * 8 + r + wn * 64 + np * 16) * 80
                                                + (g & 1) * 16 + ks * 32));
                mma_f16(c[0][2 * np],     a[0][0], a[0][1], a[0][2], a[0][3], bm[0], bm[1]);
                mma_f16(c[0][2 * np + 1], a[0][0], a[0][1], a[0][2], a[0][3], bm[2], bm[3]);
                mma_f16(c[1][2 * np],     a[1][0], a[1][1], a[1][2], a[1][3], bm[0], bm[1]);
                mma_f16(c[1][2 * np + 1], a[1][0], a[1][1], a[1][2], a[1][3], bm[2], bm[3]);
            }
        }

        if (ch < 31) {
#pragma unroll
            for (int p = 0; p < 4; p++) {
                int i = tid + p * 256;
                int row = i >> 3, c4 = i & 7;
                uint2 u = make_uint2(packh2(xr[p].x, xr[p].y), packh2(xr[p].z, xr[p].w));
                *reinterpret_cast<uint2*>(&Xs[nxt][row * 40 + c4 * 4]) = u;
            }
        }
    }

    if (z < 2) {
        // fp16 stores (Q pre-scaled)
#pragma unroll
        for (int mt = 0; mt < 2; mt++) {
            int r0 = m0 + wm * 32 + mt * 16 + qi;
#pragma unroll
            for (int nt = 0; nt < 8; nt++) {
                int col = wn * 64 + nt * 8 + 2 * qj;
                *reinterpret_cast<unsigned*>(&out[(size_t)r0 * HEAD + col]) =
                    packh2(c[mt][nt][0] * oscale, c[mt][nt][1] * oscale);
                *reinterpret_cast<unsigned*>(&out[(size_t)(r0 + 8) * HEAD + col]) =
                    packh2(c[mt][nt][2] * oscale, c[mt][nt][3] * oscale);
            }
        }
    } else {
        // V: transpose through smem -> g_vt[b][h][s] (fp16)
        __syncthreads();
        __half* T = smh;                 // [h=128][s=128], stride 136 halves
#pragma unroll
        for (int mt = 0; mt < 2; mt++) {
            int r0 = wm * 32 + mt * 16 + qi;
#pragma unroll
            for (int nt = 0; nt < 8; nt++) {
                int col = wn * 64 + nt * 8 + 2 * qj;
                T[col * 136 + r0]           = __float2half_rn(c[mt][nt][0]);
                T[(col + 1) * 136 + r0]     = __float2half_rn(c[mt][nt][1]);
                T[col * 136 + r0 + 8]       = __float2half_rn(c[mt][nt][2]);
                T[(col + 1) * 136 + r0 + 8] = __float2half_rn(c[mt][nt][3]);
            }
        }
        __syncthreads();
        // 32 lanes x 4 halves (uint2) = exactly 128 s-values per h-row
        const int b = m0 >> 11, s0 = m0 & 2047;
#pragma unroll
        for (int p = 0; p < 16; p++) {
            int h = wid + p * 8;
            uint2 v = *reinterpret_cast<const uint2*>(&T[h * 136 + lane * 4]);
            *reinterpret_cast<uint2*>(
                &g_vt[((size_t)b * HEAD + h) * SEQ + s0 + lane * 4]) = v;
        }
    }
}

// ---------------------------------------------------------------------------
// Kernel B: flash attention (fp16 mma), BN=128 key tiles, pipelined cp.async.
// BM=64, 4 warps (warp m16). Q-frags in regs. exp2-domain softmax.
// Ks 128x136 halves, Vt 128x136, Ps 64x136 (all stride 272 B = 16 mod 128).
// ---------------------------------------------------------------------------
#define KS_H (128 * 136)
#define VT_H (128 * 136)
#define PS_H (64 * 136)
#define FA_SMEM ((KS_H + VT_H + PS_H) * 2)   // 87040 B

__global__ __launch_bounds__(128, 2) void flash_mma(float* __restrict__ out)
{
    extern __shared__ __half smf[];
    const unsigned SB = (unsigned)__cvta_generic_to_shared(smf);
    __half* Ps = smf + KS_H + VT_H;
    const unsigned KsB = SB;
    const unsigned VtB = SB + KS_H * 2;
    const unsigned PsB = SB + (KS_H + VT_H) * 2;

    const int tid = threadIdx.x;
    const int wid = tid >> 5, lane = tid & 31;
    const int qi = lane >> 2, qj = lane & 3;
    const int g  = lane >> 3, r = lane & 7;
    const int l16 = lane & 15, hi16 = lane >> 4;

    // balanced heavy-first schedule (bid and bid+148 share an SM)
    const int bid = blockIdx.x;
    const int t  = (bid < 148) ? bid : 403 - bid;
    const int qt = 31 - (t >> 3);
    const int b  = t & 7;
    const int q0 = qt * 64;
    const int m0 = wid * 16;
    const int nkt = (qt >> 1) + 1;       // number of 128-wide key tiles

    const __half* kbase  = g_k  + (size_t)b * SEQ * HEAD;
    const __half* vtbase = g_vt + (size_t)b * HEAD * SEQ;

    // ---- stage Q through Ks, ldmatrix into regs ----
    {
        const __half* qb = g_q + ((size_t)b * SEQ + q0) * HEAD;
#pragma unroll
        for (int p = 0; p < 8; p++) {
            int i = tid + p * 128;
            int row = i >> 4, c4 = i & 15;
            cpasync16(KsB + (unsigned)(row * 272 + c4 * 16), qb + (size_t)row * HEAD + c4 * 8);
        }
        CP_COMMIT; CP_WAIT0;
        __syncthreads();
    }
    unsigned qa[8][4];
    {
        const unsigned aOff = (unsigned)((m0 + l16) * 272 + hi16 * 16);
#pragma unroll
        for (int ks = 0; ks < 8; ks++) ldsm4(qa[ks], KsB + aOff + ks * 32);
    }
    __syncthreads();   // Ks free for K(0)

    // prologue: issue K(0) then V(0)  (128 rows x 256 B each)
#pragma unroll
    for (int p = 0; p < 16; p++) {
        int i = tid + p * 128;
        int row = i >> 4, c4 = i & 15;
        cpasync16(KsB + (unsigned)(row * 272 + c4 * 16), kbase + (size_t)row * HEAD + c4 * 8);
    }
    CP_COMMIT;
#pragma unroll
    for (int p = 0; p < 16; p++) {
        int i = tid + p * 128;
        int h = i >> 4, c4 = i & 15;
        cpasync16(VtB + (unsigned)(h * 272 + c4 * 16), vtbase + (size_t)h * SEQ + c4 * 8);
    }
    CP_COMMIT;

    float o[16][4];
#pragma unroll
    for (int nt = 0; nt < 16; nt++)
#pragma unroll
        for (int e = 0; e < 4; e++) o[nt][e] = 0.f;
    float mx0 = -INFINITY, mx1 = -INFINITY, l0 = 0.f, l1 = 0.f;

    const int r0g = q0 + m0 + qi;
    const int r1g = r0g + 8;

    const unsigned bOff = (unsigned)(((g >> 1) * 8 + r) * 272 + (g & 1) * 16);
    const unsigned vOff = (unsigned)(((g >> 1) * 8 + r) * 272 + (g & 1) * 16);
    const unsigned pOff = (unsigned)((m0 + l16) * 272 + hi16 * 16);

    for (int kt = 0; kt < nkt; kt++) {
        CP_WAIT1;            // K(kt) done (V(kt) may still fly)
        __syncthreads();

        // ---- S = Q K^T : 8 k16 steps x 16 n-tiles ----
        float s[16][4];
#pragma unroll
        for (int nt = 0; nt < 16; nt++)
#pragma unroll
            for (int e = 0; e < 4; e++) s[nt][e] = 0.f;
#pragma unroll
        for (int ks = 0; ks < 8; ks++) {
#pragma unroll
            for (int np = 0; np < 8; np++) {
                unsigned bm[4];
                ldsm4(bm, KsB + bOff + (unsigned)(np * 4352 + ks * 32));
                mma_f16(s[2 * np],     qa[ks][0], qa[ks][1], qa[ks][2], qa[ks][3], bm[0], bm[1]);
                mma_f16(s[2 * np + 1], qa[ks][0], qa[ks][1], qa[ks][2], qa[ks][3], bm[2], bm[3]);
            }
        }
        __syncthreads();     // all warps done reading Ks

        // issue K(kt+1) (hides behind softmax + PV)
        if (kt + 1 < nkt) {
            const __half* kb = kbase + (size_t)(kt + 1) * 128 * HEAD;
#pragma unroll
            for (int p = 0; p < 16; p++) {
                int i = tid + p * 128;
                int row = i >> 4, c4 = i & 15;
                cpasync16(KsB + (unsigned)(row * 272 + c4 * 16),
                          kb + (size_t)row * HEAD + c4 * 8);
            }
        }
        CP_COMMIT;

        // causal mask on the diagonal tile (last kt)
        if (kt == nkt - 1) {
#pragma unroll
            for (int nt = 0; nt < 16; nt++) {
                int cb = kt * 128 + nt * 8 + 2 * qj;
                if (cb > r0g)     s[nt][0] = -INFINITY;
                if (cb + 1 > r0g) s[nt][1] = -INFINITY;
                if (cb > r1g)     s[nt][2] = -INFINITY;
                if (cb + 1 > r1g) s[nt][3] = -INFINITY;
            }
        }

        // ---- online softmax (exp2 domain; quad-local rows) ----
        {
            float t0 = -INFINITY, t1 = -INFINITY;
#pragma unroll
            for (int nt = 0; nt < 16; nt++) {
                t0 = fmaxf(t0, fmaxf(s[nt][0], s[nt][1]));
                t1 = fmaxf(t1, fmaxf(s[nt][2], s[nt][3]));
            }
            t0 = fmaxf(t0, __shfl_xor_sync(0xffffffffu, t0, 1));
            t0 = fmaxf(t0, __shfl_xor_sync(0xffffffffu, t0, 2));
            t1 = fmaxf(t1, __shfl_xor_sync(0xffffffffu, t1, 1));
            t1 = fmaxf(t1, __shfl_xor_sync(0xffffffffu, t1, 2));

            float mn0 = fmaxf(mx0, t0), mn1 = fmaxf(mx1, t1);
            float cr0 = exp2f(mx0 - mn0), cr1 = exp2f(mx1 - mn1);
            mx0 = mn0; mx1 = mn1;

            float rs0 = 0.f, rs1 = 0.f;
#pragma unroll
            for (int nt = 0; nt < 16; nt++) {
                s[nt][0] = exp2f(s[nt][0] - mn0);
                s[nt][1] = exp2f(s[nt][1] - mn0);
                s[nt][2] = exp2f(s[nt][2] - mn1);
                s[nt][3] = exp2f(s[nt][3] - mn1);
                rs0 += s[nt][0] + s[nt][1];
                rs1 += s[nt][2] + s[nt][3];
            }
            rs0 += __shfl_xor_sync(0xffffffffu, rs0, 1);
            rs0 += __shfl_xor_sync(0xffffffffu, rs0, 2);
            rs1 += __shfl_xor_sync(0xffffffffu, rs1, 1);
            rs1 += __shfl_xor_sync(0xffffffffu, rs1, 2);

            l0 = l0 * cr0 + rs0;
            l1 = l1 * cr1 + rs1;
#pragma unroll
            for (int nt = 0; nt < 16; nt++) {
                o[nt][0] *= cr0; o[nt][1] *= cr0;
                o[nt][2] *= cr1; o[nt][3] *= cr1;
            }
        }

        // P -> smem (fp16), 64 x 128 tile
#pragma unroll
        for (int nt = 0; nt < 16; nt++) {
            int col = nt * 8 + 2 * qj;
            *reinterpret_cast<unsigned*>(&Ps[(m0 + qi) * 136 + col]) =
                packh2(s[nt][0], s[nt][1]);
            *reinterpret_cast<unsigned*>(&Ps[(m0 + qi + 8) * 136 + col]) =
                packh2(s[nt][2], s[nt][3]);
        }

        CP_WAIT1;            // V(kt) done (K(kt+1) may still fly)
        __syncthreads();

        // ---- O += P V : 8 k16 steps ----
#pragma unroll
        for (int ks = 0; ks < 8; ks++) {
            unsigned pA[4];
            ldsm4(pA, PsB + pOff + ks * 32);
#pragma unroll
            for (int np = 0; np < 8; np++) {
                unsigned bm[4];
                ldsm4(bm, VtB + vOff + (unsigned)(np * 4352 + ks * 32));
                mma_f16(o[2 * np],     pA[0], pA[1], pA[2], pA[3], bm[0], bm[1]);
                mma_f16(o[2 * np + 1], pA[0], pA[1], pA[2], pA[3], bm[2], bm[3]);
            }
        }
        __syncthreads();     // all warps done reading Vt (and Ps)

        // issue V(kt+1)
        if (kt + 1 < nkt) {
            const __half* vb = vtbase + (size_t)(kt + 1) * 128;
#pragma unroll
            for (int p = 0; p < 16; p++) {
                int i = tid + p * 128;
                int h = i >> 4, c4 = i & 15;
                cpasync16(VtB + (unsigned)(h * 272 + c4 * 16),
                          vb + (size_t)h * SEQ + c4 * 8);
            }
        }
        CP_COMMIT;
    }

    // epilogue (fp32 out)
    {
        float inv0 = 1.f / l0, inv1 = 1.f / l1;
        float* ob = out + ((size_t)b * SEQ) * HEAD;
#pragma unroll
        for (int nt = 0; nt < 16; nt++) {
            int col = nt * 8 + 2 * qj;
            *reinterpret_cast<float2*>(&ob[(size_t)r0g * HEAD + col]) =
                make_float2(o[nt][0] * inv0, o[nt][1] * inv0);
            *reinterpret_cast<float2*>(&ob[(size_t)r1g * HEAD + col]) =
                make_float2(o[nt][2] * inv1, o[nt][3] * inv1);
        }
    }
}

// ---------------------------------------------------------------------------
extern "C" void kernel_launch(void* const* d_in, const int* in_sizes, int n_in,
                              void* d_out, int out_size)
{
    const float* x  = (const float*)d_in[0];
    const float* Wk = (const float*)d_in[1];
    const float* Wq = (const float*)d_in[2];
    const float* Wv = (const float*)d_in[3];
    float* out = (float*)d_out;

    w_prep<<<dim3(16, 3), 256>>>(Wq, Wk, Wv);
    qkv_mma<<<dim3(MTOT / 128, 1, 3), 256>>>(x);

    cudaFuncSetAttribute(flash_mma, cudaFuncAttributeMaxDynamicSharedMemorySize, FA_SMEM);
    flash_mma<<<dim3(256, 1), 128, FA_SMEM>>>(out);
}

// round 10
// speedup vs baseline: 1.0944x; 1.0944x over previous
#include <cuda_runtime.h>
#include <cuda_fp16.h>
#include <math.h>

#define EMBED 1024
#define HEAD  128
#define BATCH 8
#define SEQ   2048
#define MTOT  (BATCH*SEQ)

#define QK_SCALE 0.045084295033136845f   // log2(e) / sqrt(1024)

// Scratch (allocation-free). All values stored as fp16.
__device__ __half g_q[MTOT * HEAD];          // pre-scaled by log2(e)/32
__device__ __half g_k[MTOT * HEAD];
__device__ __half g_vt[MTOT * HEAD];         // V transposed: [b][h][s]
__device__ __half g_wt[3][HEAD][EMBED];      // W^T fp16: [z][n][k]

// ---------------------------------------------------------------------------
// helpers
// ---------------------------------------------------------------------------
__device__ __forceinline__ unsigned packh2(float a, float b) {
    __half2 h = __floats2half2_rn(a, b);
    return *reinterpret_cast<unsigned*>(&h);
}
__device__ __forceinline__ void mma_f16(float d[4],
                                        unsigned a0, unsigned a1, unsigned a2, unsigned a3,
                                        unsigned b0, unsigned b1) {
    asm volatile(
        "mma.sync.aligned.m16n8k16.row.col.f32.f16.f16.f32 "
        "{%0,%1,%2,%3}, {%4,%5,%6,%7}, {%8,%9}, {%0,%1,%2,%3};"
        : "+f"(d[0]), "+f"(d[1]), "+f"(d[2]), "+f"(d[3])
        : "r"(a0), "r"(a1), "r"(a2), "r"(a3), "r"(b0), "r"(b1));
}
__device__ __forceinline__ void ldsm4(unsigned m[4], unsigned saddr) {
    asm volatile("ldmatrix.sync.aligned.m8n8.x4.shared.b16 {%0,%1,%2,%3}, [%4];"
                 : "=r"(m[0]), "=r"(m[1]), "=r"(m[2]), "=r"(m[3]) : "r"(saddr));
}
__device__ __forceinline__ void cpasync16(unsigned dst, const void* src) {
    asm volatile("cp.async.ca.shared.global [%0], [%1], 16;" :: "r"(dst), "l"(src));
}
#define CP_COMMIT asm volatile("cp.async.commit_group;")
#define CP_WAIT0  asm volatile("cp.async.wait_group 0;" ::: "memory")
#define CP_WAIT1  asm volatile("cp.async.wait_group 1;" ::: "memory")

// ---------------------------------------------------------------------------
// Prep: transpose + fp16 round of W into g_wt[z][n][k].
// grid (128 n, 3 z) x 256 thr; thread = 4 strided loads + 1 coalesced uint2 store.
// ---------------------------------------------------------------------------
__global__ __launch_bounds__(256) void w_prep(const float* __restrict__ Wq,
                                              const float* __restrict__ Wk,
                                              const float* __restrict__ Wv)
{
    const int z = blockIdx.y;
    const float* W = (z == 0) ? Wq : (z == 1) ? Wk : Wv;
    const int n = blockIdx.x;
    const int k = threadIdx.x * 4;
    float a = W[(size_t)(k + 0) * HEAD + n];
    float b = W[(size_t)(k + 1) * HEAD + n];
    float c = W[(size_t)(k + 2) * HEAD + n];
    float d = W[(size_t)(k + 3) * HEAD + n];
    *reinterpret_cast<uint2*>(&g_wt[z][n][k]) =
        make_uint2(packh2(a, b), packh2(c, d));
}

// ---------------------------------------------------------------------------
// Kernel A: FUSED QKV projection (fp16 mma), double-buffered.
// CTA = 64 rows x 384 cols (Q|K|V), 384 threads = 12 warps (2m x 6n),
// warp tile m32 x n64 (each warp entirely inside one z: z = wn>>1).
// X loaded+converted ONCE per chunk for all three projections.
// ---------------------------------------------------------------------------
#define FXS_H (64 * 40)      // 2560 halves per X buffer
#define FWS_H (384 * 40)     // 15360 halves per W buffer (3z x 128n rows)
__global__ __launch_bounds__(384, 1) void qkv_fused(const float* __restrict__ x)
{
    __shared__ __half smh[2 * FXS_H + 2 * FWS_H];   // 71680 B
    __half* Xs[2] = { smh, smh + FXS_H };

    const int tid = threadIdx.x;
    const int wid = tid >> 5, lane = tid & 31;
    const int qi = lane >> 2, qj = lane & 3;
    const int g  = lane >> 3, r = lane & 7;
    const int l16 = lane & 15, hi16 = lane >> 4;
    const int wn = wid % 6, wm = wid / 6;            // 2m x 6n
    const int m0 = blockIdx.x * 64;

    const unsigned SB = (unsigned)__cvta_generic_to_shared(smh);
    const unsigned XsB[2] = { SB, SB + FXS_H * 2 };
    const unsigned WsB[2] = { SB + 2 * FXS_H * 2, SB + 2 * FXS_H * 2 + FWS_H * 2 };
    const __half* wsrc = &g_wt[0][0][0];             // flat rows: z*128 + n

    float c[2][8][4];
#pragma unroll
    for (int mt = 0; mt < 2; mt++)
#pragma unroll
        for (int nt = 0; nt < 8; nt++)
#pragma unroll
            for (int e = 0; e < 4; e++) c[mt][nt][e] = 0.f;

    const float* xbase = x + (size_t)m0 * EMBED;

    // prologue: stage chunk 0
    {
#pragma unroll
        for (int p = 0; p < 4; p++) {
            int i = tid + p * 384;                   // 1536 16B chunks
            int row = i >> 2, c4 = i & 3;
            cpasync16(WsB[0] + (unsigned)(row * 80 + c4 * 16),
                      wsrc + (size_t)row * EMBED + c4 * 8);
        }
        CP_COMMIT;
        if (tid < 256) {
#pragma unroll
            for (int p = 0; p < 2; p++) {
                int i = tid + p * 256;               // 512 float4
                int row = i >> 3, c4 = i & 7;
                float4 v = *reinterpret_cast<const float4*>(
                    &xbase[(size_t)row * EMBED + c4 * 4]);
                *reinterpret_cast<uint2*>(&Xs[0][row * 40 + c4 * 4]) =
                    make_uint2(packh2(v.x, v.y), packh2(v.z, v.w));
            }
        }
    }

    for (int ch = 0; ch < 32; ch++) {
        const int cur = ch & 1, nxt = cur ^ 1;
        CP_WAIT0;
        __syncthreads();

        float4 xr[2];
        if (ch < 31) {
            const int k0n = (ch + 1) * 32;
#pragma unroll
            for (int p = 0; p < 4; p++) {
                int i = tid + p * 384;
                int row = i >> 2, c4 = i & 3;
                cpasync16(WsB[nxt] + (unsigned)(row * 80 + c4 * 16),
                          wsrc + (size_t)row * EMBED + k0n + c4 * 8);
            }
            CP_COMMIT;
            if (tid < 256) {
#pragma unroll
                for (int p = 0; p < 2; p++) {
                    int i = tid + p * 256;
                    int row = i >> 3, c4 = i & 7;
                    xr[p] = *reinterpret_cast<const float4*>(
                        &xbase[(size_t)row * EMBED + k0n + c4 * 4]);
                }
            }
        }

        // compute: 2 k16 steps, warp tile m32 x n64
#pragma unroll
        for (int ks = 0; ks < 2; ks++) {
            unsigned a[2][4];
#pragma unroll
            for (int mt = 0; mt < 2; mt++)
                ldsm4(a[mt], XsB[cur] + (unsigned)((wm * 32 + mt * 16 + l16) * 80
                                                   + hi16 * 16 + ks * 32));
#pragma unroll
            for (int np = 0; np < 4; np++) {
                unsigned bm[4];
                ldsm4(bm, WsB[cur] + (unsigned)((wn * 64 + np * 16 + (g >> 1) * 8 + r) * 80
                                                + (g & 1) * 16 + ks * 32));
                mma_f16(c[0][2 * np],     a[0][0], a[0][1], a[0][2], a[0][3], bm[0], bm[1]);
                mma_f16(c[0][2 * np + 1], a[0][0], a[0][1], a[0][2], a[0][3], bm[2], bm[3]);
                mma_f16(c[1][2 * np],     a[1][0], a[1][1], a[1][2], a[1][3], bm[0], bm[1]);
                mma_f16(c[1][2 * np + 1], a[1][0], a[1][1], a[1][2], a[1][3], bm[2], bm[3]);
            }
        }

        if (ch < 31 && tid < 256) {
#pragma unroll
            for (int p = 0; p < 2; p++) {
                int i = tid + p * 256;
                int row = i >> 3, c4 = i & 7;
                *reinterpret_cast<uint2*>(&Xs[nxt][row * 40 + c4 * 4]) =
                    make_uint2(packh2(xr[p].x, xr[p].y), packh2(xr[p].z, xr[p].w));
            }
        }
    }

    // ---- epilogue ----
    if (wn < 4) {
        // Q (wn 0,1) and K (wn 2,3): direct fp16 row-major stores
        __half* out = (wn < 2) ? g_q : g_k;
        const float sc = (wn < 2) ? QK_SCALE : 1.0f;
        const int cb = (wn & 1) * 64;
#pragma unroll
        for (int mt = 0; mt < 2; mt++) {
            int r0 = m0 + wm * 32 + mt * 16 + qi;
#pragma unroll
            for (int nt = 0; nt < 8; nt++) {
                int col = cb + nt * 8 + 2 * qj;
                *reinterpret_cast<unsigned*>(&out[(size_t)r0 * HEAD + col]) =
                    packh2(c[mt][nt][0] * sc, c[mt][nt][1] * sc);
                *reinterpret_cast<unsigned*>(&out[(size_t)(r0 + 8) * HEAD + col]) =
                    packh2(c[mt][nt][2] * sc, c[mt][nt][3] * sc);
            }
        }
    }
    __syncthreads();                 // all compute done; smem reusable as T
    __half* T = smh;                 // [h=128][s=64], stride 72 halves
    if (wn >= 4) {
#pragma unroll
        for (int mt = 0; mt < 2; mt++) {
            int srow = wm * 32 + mt * 16 + qi;
#pragma unroll
            for (int nt = 0; nt < 8; nt++) {
                int h = (wn - 4) * 64 + nt * 8 + 2 * qj;
                T[h * 72 + srow]           = __float2half_rn(c[mt][nt][0]);
                T[(h + 1) * 72 + srow]     = __float2half_rn(c[mt][nt][1]);
                T[h * 72 + srow + 8]       = __float2half_rn(c[mt][nt][2]);
                T[(h + 1) * 72 + srow + 8] = __float2half_rn(c[mt][nt][3]);
            }
        }
    }
    __syncthreads();
    // cooperative V store: 128 h x 16 uint2 (4 halves) = 2048 ops
    {
        const int b = m0 >> 11, s0 = m0 & 2047;
        if (tid < 256) {
#pragma unroll
            for (int p = 0; p < 8; p++) {
                int i = tid + p * 256;
                int h = i >> 4, cc = i & 15;
                uint2 v = *reinterpret_cast<const uint2*>(&T[h * 72 + cc * 4]);
                *reinterpret_cast<uint2*>(
                    &g_vt[((size_t)b * HEAD + h) * SEQ + s0 + cc * 4]) = v;
            }
        }
    }
}

// ---------------------------------------------------------------------------
// Kernel B: flash attention (fp16 mma), BN=64 (R8 config), pipelined cp.async.
// exp2-domain softmax (g_q pre-scaled by log2(e)/32).
// ---------------------------------------------------------------------------
#define KS_H (64 * 136)
#define VT_H (128 * 72)
#define PS_H (64 * 72)
#define FA_SMEM ((KS_H + VT_H + PS_H) * 2)   // 45056 B

__global__ __launch_bounds__(128, 2) void flash_mma(float* __restrict__ out)
{
    extern __shared__ __half smf[];
    const unsigned SB = (unsigned)__cvta_generic_to_shared(smf);
    __half* Ps = smf + KS_H + VT_H;
    const unsigned KsB = SB;
    const unsigned VtB = SB + KS_H * 2;
    const unsigned PsB = SB + (KS_H + VT_H) * 2;

    const int tid = threadIdx.x;
    const int wid = tid >> 5, lane = tid & 31;
    const int qi = lane >> 2, qj = lane & 3;
    const int g  = lane >> 3, r = lane & 7;
    const int l16 = lane & 15, hi16 = lane >> 4;

    const int bid = blockIdx.x;
    const int t  = (bid < 148) ? bid : 403 - bid;
    const int qt = 31 - (t >> 3);
    const int b  = t & 7;
    const int q0 = qt * 64;
    const int m0 = wid * 16;

    const __half* kbase  = g_k  + (size_t)b * SEQ * HEAD;
    const __half* vtbase = g_vt + (size_t)b * HEAD * SEQ;

    // ---- stage Q through Ks, ldmatrix into regs ----
    {
        const __half* qb = g_q + ((size_t)b * SEQ + q0) * HEAD;
#pragma unroll
        for (int p = 0; p < 8; p++) {
            int i = tid + p * 128;
            int row = i >> 4, c4 = i & 15;
            cpasync16(KsB + (unsigned)(row * 272 + c4 * 16), qb + (size_t)row * HEAD + c4 * 8);
        }
        CP_COMMIT; CP_WAIT0;
        __syncthreads();
    }
    unsigned qa[8][4];
    {
        const unsigned aOff = (unsigned)((m0 + l16) * 272 + hi16 * 16);
#pragma unroll
        for (int ks = 0; ks < 8; ks++) ldsm4(qa[ks], KsB + aOff + ks * 32);
    }
    __syncthreads();

    // prologue: issue K(0) then V(0)
#pragma unroll
    for (int p = 0; p < 8; p++) {
        int i = tid + p * 128;
        int row = i >> 4, c4 = i & 15;
        cpasync16(KsB + (unsigned)(row * 272 + c4 * 16), kbase + (size_t)row * HEAD + c4 * 8);
    }
    CP_COMMIT;
#pragma unroll
    for (int p = 0; p < 8; p++) {
        int i = tid + p * 128;
        int h = i >> 3, c4 = i & 7;
        cpasync16(VtB + (unsigned)(h * 144 + c4 * 16), vtbase + (size_t)h * SEQ + c4 * 8);
    }
    CP_COMMIT;

    float o[16][4];
#pragma unroll
    for (int nt = 0; nt < 16; nt++)
#pragma unroll
        for (int e = 0; e < 4; e++) o[nt][e] = 0.f;
    float mx0 = -INFINITY, mx1 = -INFINITY, l0 = 0.f, l1 = 0.f;

    const int r0g = q0 + m0 + qi;
    const int r1g = r0g + 8;

    const unsigned bOff = (unsigned)(((g >> 1) * 8 + r) * 272 + (g & 1) * 16);
    const unsigned vOff = (unsigned)(((g >> 1) * 8 + r) * 144 + (g & 1) * 16);
    const unsigned pOff = (unsigned)((m0 + l16) * 144 + hi16 * 16);

    for (int kt = 0; kt <= qt; kt++) {
        CP_WAIT1;
        __syncthreads();

        // ---- S = Q K^T ----
        float s[8][4];
#pragma unroll
        for (int nt = 0; nt < 8; nt++)
#pragma unroll
            for (int e = 0; e < 4; e++) s[nt][e] = 0.f;
#pragma unroll
        for (int ks = 0; ks < 8; ks++) {
#pragma unroll
            for (int np = 0; np < 4; np++) {
                unsigned bm[4];
                ldsm4(bm, KsB + bOff + (unsigned)(np * 4352 + ks * 32));
                mma_f16(s[2 * np],     qa[ks][0], qa[ks][1], qa[ks][2], qa[ks][3], bm[0], bm[1]);
                mma_f16(s[2 * np + 1], qa[ks][0], qa[ks][1], qa[ks][2], qa[ks][3], bm[2], bm[3]);
            }
        }
        __syncthreads();

        if (kt < qt) {
            const __half* kb = kbase + (size_t)(kt + 1) * 64 * HEAD;
#pragma unroll
            for (int p = 0; p < 8; p++) {
                int i = tid + p * 128;
                int row = i >> 4, c4 = i & 15;
                cpasync16(KsB + (unsigned)(row * 272 + c4 * 16),
                          kb + (size_t)row * HEAD + c4 * 8);
            }
        }
        CP_COMMIT;

        if (kt == qt) {
#pragma unroll
            for (int nt = 0; nt < 8; nt++) {
                int cb = kt * 64 + nt * 8 + 2 * qj;
                if (cb > r0g)     s[nt][0] = -INFINITY;
                if (cb + 1 > r0g) s[nt][1] = -INFINITY;
                if (cb > r1g)     s[nt][2] = -INFINITY;
                if (cb + 1 > r1g) s[nt][3] = -INFINITY;
            }
        }

        // ---- online softmax (exp2 domain; quad-local rows) ----
        {
            float t0 = -INFINITY, t1 = -INFINITY;
#pragma unroll
            for (int nt = 0; nt < 8; nt++) {
                t0 = fmaxf(t0, fmaxf(s[nt][0], s[nt][1]));
                t1 = fmaxf(t1, fmaxf(s[nt][2], s[nt][3]));
            }
            t0 = fmaxf(t0, __shfl_xor_sync(0xffffffffu, t0, 1));
            t0 = fmaxf(t0, __shfl_xor_sync(0xffffffffu, t0, 2));
            t1 = fmaxf(t1, __shfl_xor_sync(0xffffffffu, t1, 1));
            t1 = fmaxf(t1, __shfl_xor_sync(0xffffffffu, t1, 2));

            float mn0 = fmaxf(mx0, t0), mn1 = fmaxf(mx1, t1);
            float cr0 = exp2f(mx0 - mn0), cr1 = exp2f(mx1 - mn1);
            mx0 = mn0; mx1 = mn1;

            float rs0 = 0.f, rs1 = 0.f;
#pragma unroll
            for (int nt = 0; nt < 8; nt++) {
                s[nt][0] = exp2f(s[nt][0] - mn0);
                s[nt][1] = exp2f(s[nt][1] - mn0);
                s[nt][2] = exp2f(s[nt][2] - mn1);
                s[nt][3] = exp2f(s[nt][3] - mn1);
                rs0 += s[nt][0] + s[nt][1];
                rs1 += s[nt][2] + s[nt][3];
            }
            rs0 += __shfl_xor_sync(0xffffffffu, rs0, 1);
            rs0 += __shfl_xor_sync(0xffffffffu, rs0, 2);
            rs1 += __shfl_xor_sync(0xffffffffu, rs1, 1);
            rs1 += __shfl_xor_sync(0xffffffffu, rs1, 2);

            l0 = l0 * cr0 + rs0;
            l1 = l1 * cr1 + rs1;
#pragma unroll
            for (int nt = 0; nt < 16; nt++) {
                o[nt][0] *= cr0; o[nt][1] *= cr0;
                o[nt][2] *= cr1; o[nt][3] *= cr1;
            }
        }

        // P -> smem (fp16)
#pragma unroll
        for (int nt = 0; nt < 8; nt++) {
            int col = nt * 8 + 2 * qj;
            *reinterpret_cast<unsigned*>(&Ps[(m0 + qi) * 72 + col]) =
                packh2(s[nt][0], s[nt][1]);
            *reinterpret_cast<unsigned*>(&Ps[(m0 + qi + 8) * 72 + col]) =
                packh2(s[nt][2], s[nt][3]);
        }

        CP_WAIT1;
        __syncthreads();

        // ---- O += P V : 4 k16 steps ----
#pragma unroll
        for (int ks = 0; ks < 4; ks++) {
            unsigned pA[4];
            ldsm4(pA, PsB + pOff + ks * 32);
#pragma unroll
            for (int np = 0; np < 8; np++) {
                unsigned bm[4];
                ldsm4(bm, VtB + vOff + (unsigned)(np * 2304 + ks * 32));
                mma_f16(o[2 * np],     pA[0], pA[1], pA[2], pA[3], bm[0], bm[1]);
                mma_f16(o[2 * np + 1], pA[0], pA[1], pA[2], pA[3], bm[2], bm[3]);
            }
        }
        __syncthreads();

        if (kt < qt) {
            const __half* vb = vtbase + (size_t)(kt + 1) * 64;
#pragma unroll
            for (int p = 0; p < 8; p++) {
                int i = tid + p * 128;
                int h = i >> 3, c4 = i & 7;
                cpasync16(VtB + (unsigned)(h * 144 + c4 * 16),
                          vb + (size_t)h * SEQ + c4 * 8);
            }
        }
        CP_COMMIT;
    }

    // epilogue (fp32 out)
    {
        float inv0 = 1.f / l0, inv1 = 1.f / l1;
        float* ob = out + ((size_t)b * SEQ) * HEAD;
#pragma unroll
        for (int nt = 0; nt < 16; nt++) {
            int col = nt * 8 + 2 * qj;
            *reinterpret_cast<float2*>(&ob[(size_t)r0g * HEAD + col]) =
                make_float2(o[nt][0] * inv0, o[nt][1] * inv0);
            *reinterpret_cast<float2*>(&ob[(size_t)r1g * HEAD + col]) =
                make_float2(o[nt][2] * inv1, o[nt][3] * inv1);
        }
    }
}

// ---------------------------------------------------------------------------
extern "C" void kernel_launch(void* const* d_in, const int* in_sizes, int n_in,
                              void* d_out, int out_size)
{
    const float* x  = (const float*)d_in[0];
    const float* Wk = (const float*)d_in[1];
    const float* Wq = (const float*)d_in[2];
    const float* Wv = (const float*)d_in[3];
    float* out = (float*)d_out;

    w_prep<<<dim3(HEAD, 3), 256>>>(Wq, Wk, Wv);
    qkv_fused<<<MTOT / 64, 384>>>(x);

    cudaFuncSetAttribute(flash_mma, cudaFuncAttributeMaxDynamicSharedMemorySize, FA_SMEM);
    flash_mma<<<dim3(256, 1), 128, FA_SMEM>>>(out);
}